// round 2
// baseline (speedup 1.0000x reference)
#include <cuda_runtime.h>

// Row size in elements: C*W*H = 512*7*7 (fixed per metadata).
#define ROW_ELEMS 25088
#define ROW_VEC4  (ROW_ELEMS / 4)   // 6272 float4 per row

// Single fused kernel: one block per output row (r = 3*p + j).
// Each block derives its source input row from blockIdx + obj_num, then does
// a vectorized float4 row copy. Index math is ~O(32) int ops per block,
// amortized over a 100 KB copy.
__global__ void __launch_bounds__(256) gather_fused_kernel(
    const float4* __restrict__ in, float4* __restrict__ out,
    const int* __restrict__ obj_num, int n_images) {

    long long r = blockIdx.x;
    int p = (int)(r / 3);     // global pair index
    int j = (int)(r % 3);     // 0 = o1 feat, 1 = o2 feat, 2 = union feat

    // Locate the image containing pair p (n_images <= 16; obj_num hits L1/L2
    // after the first block touches it).
    int pair_base = 0;        // pairs before this image
    int row_begin = 0;        // input rows before this image
    int n = 0;
    for (int i = 0; i < n_images; ++i) {
        n = obj_num[i];
        int np = n * (n - 1) / 2;
        if (p < pair_base + np) break;
        pair_base += np;
        row_begin += n * (n + 1) / 2;
    }
    int u = p - pair_base;    // pair index within image

    // Invert row-major triangular enumeration to (o1, o2).
    int o1 = 0, s = 0;
    while (s + (n - 1 - o1) <= u) {
        s += (n - 1 - o1);
        ++o1;
    }
    int o2 = o1 + 1 + (u - s);

    int src_row = (j == 0) ? (row_begin + o1)
                : (j == 1) ? (row_begin + o2)
                           : (row_begin + n + u);

    const float4* __restrict__ src = in + (long long)src_row * ROW_VEC4;
    float4* __restrict__ dst = out + r * ROW_VEC4;

    if (j == 2) {
        // Union row: read exactly once across the whole kernel -> stream
        // (evict-first) so it doesn't displace reusable single-object rows.
        #pragma unroll 8
        for (int i = threadIdx.x; i < ROW_VEC4; i += 256) {
            float4 v = __ldcs(&src[i]);
            __stcs(&dst[i], v);
        }
    } else {
        // Single-object row: reused up to (n-1) times -> default caching for
        // the read, streaming (evict-first) for the write.
        #pragma unroll 8
        for (int i = threadIdx.x; i < ROW_VEC4; i += 256) {
            float4 v = src[i];
            __stcs(&dst[i], v);
        }
    }
}

extern "C" void kernel_launch(void* const* d_in, const int* in_sizes, int n_in,
                              void* d_out, int out_size) {
    const float* feats = (const float*)d_in[0];
    // d_in[1] is batch_size scalar; d_in[2] is obj_num array.
    const int* obj_num = (const int*)d_in[2];
    int n_images = in_sizes[2];

    int out_rows = out_size / ROW_ELEMS;      // = 3 * P

    gather_fused_kernel<<<out_rows, 256>>>((const float4*)feats, (float4*)d_out,
                                           obj_num, n_images);
}

// round 3
// speedup vs baseline: 1.0626x; 1.0626x over previous
#include <cuda_runtime.h>

// Row size in elements: C*W*H = 512*7*7 (fixed per metadata).
#define ROW_ELEMS 25088
#define ROW_VEC4  (ROW_ELEMS / 4)   // 6272 float4 per row

// Single fused kernel: one block per output row (r = 3*p + j).
// Each block derives its source input row from blockIdx + obj_num (tiny
// scalar loop, amortized over a 100 KB copy), then does a plain vectorized
// float4 row copy. NO cache-policy hints: R2 showed .cs stores drop achieved
// HBM BW from 6023 -> 5445 GB/s with zero traffic savings.
__global__ void __launch_bounds__(256) gather_fused_kernel(
    const float4* __restrict__ in, float4* __restrict__ out,
    const int* __restrict__ obj_num, int n_images) {

    long long r = blockIdx.x;
    int p = (int)(r / 3);     // global pair index
    int j = (int)(r % 3);     // 0 = o1 feat, 1 = o2 feat, 2 = union feat

    // Locate the image containing pair p (n_images <= 16).
    int pair_base = 0;        // pairs before this image
    int row_begin = 0;        // input rows before this image
    int n = 0;
    for (int i = 0; i < n_images; ++i) {
        n = obj_num[i];
        int np = n * (n - 1) / 2;
        if (p < pair_base + np) break;
        pair_base += np;
        row_begin += n * (n + 1) / 2;
    }
    int u = p - pair_base;    // pair index within image

    // Invert row-major triangular enumeration to (o1, o2).
    int o1 = 0, s = 0;
    while (s + (n - 1 - o1) <= u) {
        s += (n - 1 - o1);
        ++o1;
    }
    int o2 = o1 + 1 + (u - s);

    int src_row = (j == 0) ? (row_begin + o1)
                : (j == 1) ? (row_begin + o2)
                           : (row_begin + n + u);

    const float4* __restrict__ src = in + (long long)src_row * ROW_VEC4;
    float4* __restrict__ dst = out + r * ROW_VEC4;

    #pragma unroll 8
    for (int i = threadIdx.x; i < ROW_VEC4; i += 256) {
        dst[i] = src[i];
    }
}

extern "C" void kernel_launch(void* const* d_in, const int* in_sizes, int n_in,
                              void* d_out, int out_size) {
    const float* feats = (const float*)d_in[0];
    // d_in[1] is batch_size scalar; d_in[2] is obj_num array.
    const int* obj_num = (const int*)d_in[2];
    int n_images = in_sizes[2];

    int out_rows = out_size / ROW_ELEMS;      // = 3 * P

    gather_fused_kernel<<<out_rows, 256>>>((const float4*)feats, (float4*)d_out,
                                           obj_num, n_images);
}